// round 9
// baseline (speedup 1.0000x reference)
#include <cuda_runtime.h>
#include <cuda_bf16.h>
#include <math.h>
#include <stdint.h>

// ---------------- scratch (device globals; no allocs allowed) ----------------
__device__ float g_z[512 * 448];            // z padded to 448 cols (cols 432..447 = 0)
__device__ float g_part[18 * 512 * 512];    // split-K partials
__device__ float g_h1[512 * 512];           // relu(inter@pw0+pb0)

// pack two fp32 -> bf16x2 (lo -> low half)
__device__ __forceinline__ uint32_t pack_bf16(float lo, float hi) {
    uint32_t r;
    asm("cvt.rn.bf16x2.f32 %0, %1, %2;" : "=r"(r) : "f"(hi), "f"(lo));
    return r;
}
__device__ __forceinline__ uint32_t hmul2(uint32_t a, uint32_t b) {
    uint32_t r;
    asm("mul.rn.bf16x2 %0, %1, %2;" : "=r"(r) : "r"(a), "r"(b));
    return r;
}
__device__ __forceinline__ uint32_t smem_u32(const void* p) {
    uint32_t a;
    asm("{ .reg .u64 t; cvta.to.shared.u64 t, %1; cvt.u32.u64 %0, t; }" : "=r"(a) : "l"(p));
    return a;
}
__device__ __forceinline__ void cpasync64(uint32_t dst, const void* src) {
    asm volatile(
        "cp.async.cg.shared.global [%0], [%1], 16;\n\t"
        "cp.async.cg.shared.global [%2], [%3], 16;\n\t"
        "cp.async.cg.shared.global [%4], [%5], 16;\n\t"
        "cp.async.cg.shared.global [%6], [%7], 16;"
        :: "r"(dst), "l"(src),
           "r"(dst + 16), "l"((const char*)src + 16),
           "r"(dst + 32), "l"((const char*)src + 32),
           "r"(dst + 48), "l"((const char*)src + 48) : "memory");
}
#define CP_COMMIT() asm volatile("cp.async.commit_group;" ::: "memory")
#define CP_WAIT2()  asm volatile("cp.async.wait_group 2;" ::: "memory")

// ---------------- kernel 1: dense MLP (4 batch rows / block) ----------------
__global__ void dense_mlp_kernel(const float* __restrict__ x,
                                 const float* __restrict__ dw0, const float* __restrict__ db0,
                                 const float* __restrict__ dw1, const float* __restrict__ db1,
                                 const float* __restrict__ dw2, const float* __restrict__ db2,
                                 const float* __restrict__ dw3, const float* __restrict__ db3) {
    __shared__ float xs[4][13];
    __shared__ float h0[4][512];
    __shared__ float h1[4][256];
    __shared__ float h2[4][64];
    const int r0 = blockIdx.x * 4;
    const int tid = threadIdx.x;

    if (tid < 52) xs[tid / 13][tid % 13] = x[(r0 + tid / 13) * 13 + tid % 13];
    __syncthreads();

    #pragma unroll
    for (int jj = 0; jj < 2; jj++) {
        int j = tid + jj * 256;
        float a[4];
        float b = db0[j];
        #pragma unroll
        for (int r = 0; r < 4; r++) a[r] = b;
        #pragma unroll
        for (int i = 0; i < 13; i++) {
            float w = dw0[i * 512 + j];
            #pragma unroll
            for (int r = 0; r < 4; r++) a[r] += xs[r][i] * w;
        }
        #pragma unroll
        for (int r = 0; r < 4; r++) h0[r][j] = fmaxf(a[r], 0.f);
    }
    __syncthreads();

    {
        float a[4];
        float b = db1[tid];
        #pragma unroll
        for (int r = 0; r < 4; r++) a[r] = b;
        #pragma unroll 8
        for (int i = 0; i < 512; i++) {
            float w = dw1[i * 256 + tid];
            #pragma unroll
            for (int r = 0; r < 4; r++) a[r] += h0[r][i] * w;
        }
        #pragma unroll
        for (int r = 0; r < 4; r++) h1[r][tid] = fmaxf(a[r], 0.f);
    }
    __syncthreads();

    if (tid < 64) {
        float a[4];
        float b = db2[tid];
        #pragma unroll
        for (int r = 0; r < 4; r++) a[r] = b;
        #pragma unroll 8
        for (int i = 0; i < 256; i++) {
            float w = dw2[i * 64 + tid];
            #pragma unroll
            for (int r = 0; r < 4; r++) a[r] += h1[r][i] * w;
        }
        #pragma unroll
        for (int r = 0; r < 4; r++) h2[r][tid] = fmaxf(a[r], 0.f);
    }
    __syncthreads();

    if (tid < 16) {
        float a[4];
        float b = db3[tid];
        #pragma unroll
        for (int r = 0; r < 4; r++) a[r] = b;
        #pragma unroll
        for (int i = 0; i < 64; i++) {
            float w = dw3[i * 16 + tid];
            #pragma unroll
            for (int r = 0; r < 4; r++) a[r] += h2[r][i] * w;
        }
        #pragma unroll
        for (int r = 0; r < 4; r++) g_z[(size_t)(r0 + r) * 448 + tid] = a[r];
    }
    if (tid >= 64 && tid < 128) {
        int u = tid - 64;
        g_z[(size_t)(r0 + u / 16) * 448 + 432 + (u % 16)] = 0.f;
    }
}

// ---------------- kernel 2: embedding gather -> z[:,16:432] ----------------
__global__ void embed_kernel(const void* __restrict__ sp, const float* __restrict__ emb) {
    int t = blockIdx.x * blockDim.x + threadIdx.x;
    if (t >= 512 * 26) return;
    const int* si = (const int*)sp;
    bool is64 = (si[1] == 0 && si[3] == 0 && si[5] == 0);
    long long v = is64 ? ((const long long*)sp)[t] : (long long)si[t];
    int id = (int)((v + 1) % 100000);
    int b = t / 26, f = t - b * 26;
    const float4* src = (const float4*)(emb + ((size_t)f * 100000 + id) * 16);
    float4* dst = (float4*)(g_z + (size_t)b * 448 + 16 + f * 16);
    dst[0] = src[0]; dst[1] = src[1]; dst[2] = src[2]; dst[3] = src[3];
}

// ---------------- kernel 3: interaction GEMM -------------------------------
// C[512,512] = A @ W0, A[b, p*432+q] = z[b,p]*z[b,q]
// CTA: 128m x 128n, 24 p per split (18 splits -> 288 CTAs = 2/SM).
// A fragments built IN REGISTERS (zq window cache + zp broadcast LDS + mul.bf16x2).
// B: fp32 W0 rows cp.async'd directly ([32k][132-fp32 pitch], 4-stage ring);
//    fragments via conflict-free strided LDS.32 + cvt to bf16x2. No convert pass.
#define BPITCH  132                         // fp32 words per k-row (132*4=528B)
#define BSTAGE  16896u                      // 32 * 528
#define GOFF_ZP 0u                          // [128][25] f32 = 12800
#define GOFF_B  12800u                      // 4 x 16896
#define GSMEM   80384u

__global__ __launch_bounds__(256, 2) void inter_gemm_kernel(const float* __restrict__ W0) {
    extern __shared__ char smem[];
    const uint32_t sb = smem_u32(smem);
    float* zp_s = (float*)(smem + GOFF_ZP);   // row pitch 25 floats

    const int tid = threadIdx.x;
    const int warp = tid >> 5, lane = tid & 31;
    const int g = lane >> 2, c = lane & 3;
    const int m0 = blockIdx.x * 128;          // m fastest -> L2 dedupe of W0 stream
    const int n0 = blockIdx.y * 128;
    const int p0 = blockIdx.z * 24;
    const int wm0 = (warp >> 2) * 64, wn0 = (warp & 3) * 32;

    // ---- load zp [128][24] ----
    for (int i = tid; i < 128 * 24; i += 256) {
        int b = i / 24, j = i - b * 24;
        zp_s[b * 25 + j] = g_z[(size_t)(m0 + b) * 448 + p0 + j];
    }
    __syncthreads();

    // ---- B cp.async params: thread -> (k row, 64B n-chunk) ----
    const int brow = tid >> 3;                // k row 0..31
    const int bcol = (tid & 7) * 16;          // fp32 offset within row (16 f32 = 64B)
    const uint32_t bdst = sb + GOFF_B + (uint32_t)(brow * 528 + bcol * 4);

#define ISSUE_B(ST) do {                                                       \
        int qc_ = (ST) / 24, pp_ = (ST) - qc_ * 24;                            \
        long long gk_ = (long long)(p0 + pp_) * 432 + qc_ * 32 + brow;         \
        if (gk_ > 186623LL) gk_ = 186623LL;  /* padded q: A==0 there */        \
        cpasync64(bdst + ((ST) & 3) * BSTAGE, W0 + gk_ * 512 + n0 + bcol);     \
    } while (0)

    ISSUE_B(0); CP_COMMIT();
    ISSUE_B(1); CP_COMMIT();
    ISSUE_B(2); CP_COMMIT();

    // ---- zq register cache: 8 rows x 4 k-pair slots (k = 2c + 8j) ----
    uint32_t zq_c[8][4];
#define LOAD_ZQ(W) do {                                                        \
        _Pragma("unroll")                                                      \
        for (int rr_ = 0; rr_ < 8; rr_++) {                                    \
            int row_ = m0 + wm0 + (rr_ >> 1) * 16 + ((rr_ & 1) << 3) + g;      \
            const float* zr_ = g_z + (size_t)row_ * 448 + (W) * 32 + 2 * c;    \
            _Pragma("unroll")                                                  \
            for (int j_ = 0; j_ < 4; j_++) {                                   \
                float2 v_ = *(const float2*)(zr_ + 8 * j_);                    \
                zq_c[rr_][j_] = pack_bf16(v_.x, v_.y);                         \
            }                                                                  \
        }                                                                      \
    } while (0)

    LOAD_ZQ(0);

    float acc[4][4][4];
    #pragma unroll
    for (int mi = 0; mi < 4; mi++)
        #pragma unroll
        for (int nj = 0; nj < 4; nj++)
            #pragma unroll
            for (int k = 0; k < 4; k++) acc[mi][nj][k] = 0.f;

    for (int s = 0; s < 336; s++) {
        CP_WAIT2();
        __syncthreads();                       // B[s] visible; buffer (s+3)&3 free
        if (s + 3 < 336) ISSUE_B(s + 3);
        CP_COMMIT();

        const int p = s % 24;
        // zp for this stage's 8 rows (broadcast LDS within each quad)
        uint32_t zp2[8];
        #pragma unroll
        for (int rr = 0; rr < 8; rr++) {
            int row = wm0 + (rr >> 1) * 16 + ((rr & 1) << 3) + g;
            float v = zp_s[row * 25 + p];
            zp2[rr] = pack_bf16(v, v);
        }

        const float* Bs = (const float*)(smem + GOFF_B + (uint32_t)((s & 3) * BSTAGE));

        #pragma unroll
        for (int ks = 0; ks < 2; ks++) {
            // B fragments: strided LDS.32 (pitch 132 => conflict-free) + pack
            uint32_t bfr[4][2];
            #pragma unroll
            for (int nj = 0; nj < 4; nj++) {
                const float* bp = Bs + (wn0 + nj * 8 + g);
                int kb = ks * 16 + 2 * c;
                bfr[nj][0] = pack_bf16(bp[kb * BPITCH],       bp[(kb + 1) * BPITCH]);
                bfr[nj][1] = pack_bf16(bp[(kb + 8) * BPITCH], bp[(kb + 9) * BPITCH]);
            }
            #pragma unroll
            for (int mi = 0; mi < 4; mi++) {
                uint32_t a0 = hmul2(zp2[2 * mi],     zq_c[2 * mi][ks * 2]);
                uint32_t a1 = hmul2(zp2[2 * mi + 1], zq_c[2 * mi + 1][ks * 2]);
                uint32_t a2 = hmul2(zp2[2 * mi],     zq_c[2 * mi][ks * 2 + 1]);
                uint32_t a3 = hmul2(zp2[2 * mi + 1], zq_c[2 * mi + 1][ks * 2 + 1]);
                #pragma unroll
                for (int nj = 0; nj < 4; nj++) {
                    asm volatile(
                        "mma.sync.aligned.m16n8k16.row.col.f32.bf16.bf16.f32 "
                        "{%0,%1,%2,%3},{%4,%5,%6,%7},{%8,%9},{%0,%1,%2,%3};"
                        : "+f"(acc[mi][nj][0]), "+f"(acc[mi][nj][1]),
                          "+f"(acc[mi][nj][2]), "+f"(acc[mi][nj][3])
                        : "r"(a0), "r"(a1), "r"(a2), "r"(a3),
                          "r"(bfr[nj][0]), "r"(bfr[nj][1]));
                }
            }
        }

        // reload zq register cache at window boundary
        if (p == 23 && s + 1 < 336) LOAD_ZQ((s + 1) / 24);
    }

    // epilogue: write split partials
    #pragma unroll
    for (int mi = 0; mi < 4; mi++)
        #pragma unroll
        for (int nj = 0; nj < 4; nj++) {
            int row = m0 + wm0 + 16 * mi + g;
            int col = n0 + wn0 + 8 * nj + 2 * c;
            float* d0 = g_part + ((size_t)blockIdx.z * 512 + row) * 512 + col;
            float* d1 = g_part + ((size_t)blockIdx.z * 512 + row + 8) * 512 + col;
            *(float2*)d0 = make_float2(acc[mi][nj][0], acc[mi][nj][1]);
            *(float2*)d1 = make_float2(acc[mi][nj][2], acc[mi][nj][3]);
        }
}
#undef ISSUE_B
#undef LOAD_ZQ

// ---------------- kernel 4: reduce split-K partials + bias + relu ----------
__global__ void reduce_relu_kernel(const float* __restrict__ pb0) {
    int b = blockIdx.x;
    for (int j = threadIdx.x; j < 512; j += 256) {
        float s = pb0[j];
        #pragma unroll
        for (int sp = 0; sp < 18; sp++)
            s += g_part[((size_t)sp * 512 + b) * 512 + j];
        g_h1[(size_t)b * 512 + j] = fmaxf(s, 0.f);
    }
}

// ---------------- kernel 5: prediction MLP + sigmoid -----------------------
__global__ void pred_kernel(const float* __restrict__ pw1, const float* __restrict__ pb1,
                            const float* __restrict__ pw2, const float* __restrict__ pb2,
                            float* __restrict__ out) {
    __shared__ float h1s[4][512];
    __shared__ float h2s[4][256];
    __shared__ float red[4][8];
    const int r0 = blockIdx.x * 4;
    const int tid = threadIdx.x;

    for (int i = tid; i < 2048; i += 256)
        h1s[i >> 9][i & 511] = g_h1[(size_t)(r0 + (i >> 9)) * 512 + (i & 511)];
    __syncthreads();

    {
        float a[4];
        float b = pb1[tid];
        #pragma unroll
        for (int r = 0; r < 4; r++) a[r] = b;
        #pragma unroll 8
        for (int i = 0; i < 512; i++) {
            float w = pw1[i * 256 + tid];
            #pragma unroll
            for (int r = 0; r < 4; r++) a[r] += h1s[r][i] * w;
        }
        #pragma unroll
        for (int r = 0; r < 4; r++) h2s[r][tid] = fmaxf(a[r], 0.f);
    }
    __syncthreads();

    float w2 = pw2[tid];
    int lane = tid & 31, wp = tid >> 5;
    #pragma unroll
    for (int r = 0; r < 4; r++) {
        float v = h2s[r][tid] * w2;
        #pragma unroll
        for (int o = 16; o; o >>= 1) v += __shfl_xor_sync(0xffffffffu, v, o);
        if (lane == 0) red[r][wp] = v;
    }
    __syncthreads();
    if (tid < 4) {
        float s = pb2[0];
        #pragma unroll
        for (int w = 0; w < 8; w++) s += red[tid][w];
        out[r0 + tid] = 1.f / (1.f + expf(-s));
    }
}

// ---------------- launch ----------------------------------------------------
extern "C" void kernel_launch(void* const* d_in, const int* in_sizes, int n_in,
                              void* d_out, int out_size) {
    const float* x   = (const float*)d_in[0];
    const void*  sp  = d_in[1];
    const float* emb = (const float*)d_in[2];
    const float* dw0 = (const float*)d_in[3];
    const float* db0 = (const float*)d_in[4];
    const float* dw1 = (const float*)d_in[5];
    const float* db1 = (const float*)d_in[6];
    const float* dw2 = (const float*)d_in[7];
    const float* db2 = (const float*)d_in[8];
    const float* dw3 = (const float*)d_in[9];
    const float* db3 = (const float*)d_in[10];
    const float* pw0 = (const float*)d_in[11];
    const float* pb0 = (const float*)d_in[12];
    const float* pw1 = (const float*)d_in[13];
    const float* pb1 = (const float*)d_in[14];
    const float* pw2 = (const float*)d_in[15];
    const float* pb2 = (const float*)d_in[16];
    float* out = (float*)d_out;

    cudaFuncSetAttribute(inter_gemm_kernel,
                         cudaFuncAttributeMaxDynamicSharedMemorySize, (int)GSMEM);

    dense_mlp_kernel<<<128, 256>>>(x, dw0, db0, dw1, db1, dw2, db2, dw3, db3);
    embed_kernel<<<52, 256>>>(sp, emb);
    inter_gemm_kernel<<<dim3(4, 4, 18), 256, GSMEM>>>(pw0);
    reduce_relu_kernel<<<512, 256>>>(pb0);
    pred_kernel<<<128, 256>>>(pw1, pb1, pw2, pb2, out);
}

// round 10
// speedup vs baseline: 1.2509x; 1.2509x over previous
#include <cuda_runtime.h>
#include <cuda_bf16.h>
#include <math.h>
#include <stdint.h>

// ---------------- scratch (device globals; no allocs allowed) ----------------
__device__ float g_z[512 * 448];            // z padded to 448 cols (cols 432..447 = 0)
__device__ float g_part[18 * 512 * 512];    // split-K partials
__device__ float g_h1[512 * 512];           // relu(inter@pw0+pb0)
// W0 converted to bf16, SAME [k][n] layout (no transpose)
__device__ __nv_bfloat16 g_w0c[(size_t)186624 * 512];

// pack two fp32 -> bf16x2 (lo -> low half)
__device__ __forceinline__ uint32_t pack_bf16(float lo, float hi) {
    uint32_t r;
    asm("cvt.rn.bf16x2.f32 %0, %1, %2;" : "=r"(r) : "f"(hi), "f"(lo));
    return r;
}
__device__ __forceinline__ uint32_t hmul2(uint32_t a, uint32_t b) {
    uint32_t r;
    asm("mul.rn.bf16x2 %0, %1, %2;" : "=r"(r) : "r"(a), "r"(b));
    return r;
}
__device__ __forceinline__ uint32_t smem_u32(const void* p) {
    uint32_t a;
    asm("{ .reg .u64 t; cvta.to.shared.u64 t, %1; cvt.u32.u64 %0, t; }" : "=r"(a) : "l"(p));
    return a;
}
#define LDSM4T(R0, R1, R2, R3, ADDR)                                           \
    asm volatile("ldmatrix.sync.aligned.m8n8.x4.trans.shared.b16 {%0,%1,%2,%3}, [%4];" \
                 : "=r"(R0), "=r"(R1), "=r"(R2), "=r"(R3) : "r"(ADDR))
__device__ __forceinline__ void cpasync32(uint32_t dst, const void* src) {
    asm volatile(
        "cp.async.cg.shared.global [%0], [%1], 16;\n\t"
        "cp.async.cg.shared.global [%2], [%3], 16;"
        :: "r"(dst), "l"(src), "r"(dst + 16), "l"((const char*)src + 16) : "memory");
}
#define CP_COMMIT() asm volatile("cp.async.commit_group;" ::: "memory")
#define CP_WAIT2()  asm volatile("cp.async.wait_group 2;" ::: "memory")

// ---------------- kernel 0: elementwise convert W0 -> bf16 (same layout) ----
__global__ void convert_w0_kernel(const float* __restrict__ W0) {
    size_t i = ((size_t)blockIdx.x * 256 + threadIdx.x) * 8;
    float4 a = *(const float4*)(W0 + i);
    float4 b = *(const float4*)(W0 + i + 4);
    uint4 o;
    o.x = pack_bf16(a.x, a.y); o.y = pack_bf16(a.z, a.w);
    o.z = pack_bf16(b.x, b.y); o.w = pack_bf16(b.z, b.w);
    *(uint4*)(g_w0c + i) = o;
}

// ---------------- kernel 1: dense MLP (4 batch rows / block) ----------------
__global__ void dense_mlp_kernel(const float* __restrict__ x,
                                 const float* __restrict__ dw0, const float* __restrict__ db0,
                                 const float* __restrict__ dw1, const float* __restrict__ db1,
                                 const float* __restrict__ dw2, const float* __restrict__ db2,
                                 const float* __restrict__ dw3, const float* __restrict__ db3) {
    __shared__ float xs[4][13];
    __shared__ float h0[4][512];
    __shared__ float h1[4][256];
    __shared__ float h2[4][64];
    const int r0 = blockIdx.x * 4;
    const int tid = threadIdx.x;

    if (tid < 52) xs[tid / 13][tid % 13] = x[(r0 + tid / 13) * 13 + tid % 13];
    __syncthreads();

    #pragma unroll
    for (int jj = 0; jj < 2; jj++) {
        int j = tid + jj * 256;
        float a[4];
        float b = db0[j];
        #pragma unroll
        for (int r = 0; r < 4; r++) a[r] = b;
        #pragma unroll
        for (int i = 0; i < 13; i++) {
            float w = dw0[i * 512 + j];
            #pragma unroll
            for (int r = 0; r < 4; r++) a[r] += xs[r][i] * w;
        }
        #pragma unroll
        for (int r = 0; r < 4; r++) h0[r][j] = fmaxf(a[r], 0.f);
    }
    __syncthreads();

    {
        float a[4];
        float b = db1[tid];
        #pragma unroll
        for (int r = 0; r < 4; r++) a[r] = b;
        #pragma unroll 8
        for (int i = 0; i < 512; i++) {
            float w = dw1[i * 256 + tid];
            #pragma unroll
            for (int r = 0; r < 4; r++) a[r] += h0[r][i] * w;
        }
        #pragma unroll
        for (int r = 0; r < 4; r++) h1[r][tid] = fmaxf(a[r], 0.f);
    }
    __syncthreads();

    if (tid < 64) {
        float a[4];
        float b = db2[tid];
        #pragma unroll
        for (int r = 0; r < 4; r++) a[r] = b;
        #pragma unroll 8
        for (int i = 0; i < 256; i++) {
            float w = dw2[i * 64 + tid];
            #pragma unroll
            for (int r = 0; r < 4; r++) a[r] += h1[r][i] * w;
        }
        #pragma unroll
        for (int r = 0; r < 4; r++) h2[r][tid] = fmaxf(a[r], 0.f);
    }
    __syncthreads();

    if (tid < 16) {
        float a[4];
        float b = db3[tid];
        #pragma unroll
        for (int r = 0; r < 4; r++) a[r] = b;
        #pragma unroll
        for (int i = 0; i < 64; i++) {
            float w = dw3[i * 16 + tid];
            #pragma unroll
            for (int r = 0; r < 4; r++) a[r] += h2[r][i] * w;
        }
        #pragma unroll
        for (int r = 0; r < 4; r++) g_z[(size_t)(r0 + r) * 448 + tid] = a[r];
    }
    if (tid >= 64 && tid < 128) {
        int u = tid - 64;
        g_z[(size_t)(r0 + u / 16) * 448 + 432 + (u % 16)] = 0.f;
    }
}

// ---------------- kernel 2: embedding gather -> z[:,16:432] ----------------
__global__ void embed_kernel(const void* __restrict__ sp, const float* __restrict__ emb) {
    int t = blockIdx.x * blockDim.x + threadIdx.x;
    if (t >= 512 * 26) return;
    const int* si = (const int*)sp;
    bool is64 = (si[1] == 0 && si[3] == 0 && si[5] == 0);
    long long v = is64 ? ((const long long*)sp)[t] : (long long)si[t];
    int id = (int)((v + 1) % 100000);
    int b = t / 26, f = t - b * 26;
    const float4* src = (const float4*)(emb + ((size_t)f * 100000 + id) * 16);
    float4* dst = (float4*)(g_z + (size_t)b * 448 + 16 + f * 16);
    dst[0] = src[0]; dst[1] = src[1]; dst[2] = src[2]; dst[3] = src[3];
}

// ---------------- kernel 3: interaction GEMM -------------------------------
// C[512,512] = A @ W0, A[b, p*432+q] = z[b,p]*z[b,q]
// CTA: 128m x 128n, 24 p per split (18 splits -> 288 CTAs = 2/SM).
// A fragments built IN REGISTERS (zq window cache + zp broadcast LDS + mul.bf16x2).
// B: bf16 W0c [k][n] rows cp.async'd directly ([32k][128n], pitch 272B, 4-ring);
//    fragments via ldmatrix.x4.trans (conflict-free at pitch 272B).
#define BPITCH  272u                        // bytes per k-row (128 bf16 = 256B data + 16 pad)
#define BSTAGE  8704u                       // 32 * 272
#define GOFF_ZP 0u                          // [128][25] f32 = 12800
#define GOFF_B  12800u                      // 4 x 8704
#define GSMEM   47616u

__global__ __launch_bounds__(256, 2) void inter_gemm_kernel() {
    extern __shared__ char smem[];
    const uint32_t sb = smem_u32(smem);
    float* zp_s = (float*)(smem + GOFF_ZP);   // row pitch 25 floats

    const int tid = threadIdx.x;
    const int warp = tid >> 5, lane = tid & 31;
    const int g = lane >> 2, c = lane & 3;
    const int m0 = blockIdx.x * 128;          // m fastest -> L2 dedupe of W0c stream
    const int n0 = blockIdx.y * 128;
    const int p0 = blockIdx.z * 24;
    const int wm0 = (warp >> 2) * 64, wn0 = (warp & 3) * 32;

    // ---- load zp [128][24] ----
    for (int i = tid; i < 128 * 24; i += 256) {
        int b = i / 24, j = i - b * 24;
        zp_s[b * 25 + j] = g_z[(size_t)(m0 + b) * 448 + p0 + j];
    }
    __syncthreads();

    // ---- B cp.async params: thread -> (k row, 32B n-chunk) ----
    const int brow = tid >> 3;                // k row 0..31
    const int bco = (tid & 7) * 16;           // bf16 element offset (16 elems = 32B)
    const uint32_t bdst = sb + GOFF_B + (uint32_t)(brow * BPITCH + bco * 2);

#define ISSUE_B(ST) do {                                                       \
        int qc_ = (ST) / 24, pp_ = (ST) - qc_ * 24;                            \
        long long gk_ = (long long)(p0 + pp_) * 432 + qc_ * 32 + brow;         \
        if (gk_ > 186623LL) gk_ = 186623LL;  /* padded q: A==0 there */        \
        cpasync32(bdst + ((ST) & 3) * BSTAGE, g_w0c + gk_ * 512 + n0 + bco);   \
    } while (0)

    ISSUE_B(0); CP_COMMIT();
    ISSUE_B(1); CP_COMMIT();
    ISSUE_B(2); CP_COMMIT();

    // ---- zq register cache: 8 rows x 4 k-pair slots (k = 2c + 8j) ----
    uint32_t zq_c[8][4];
#define LOAD_ZQ(W) do {                                                        \
        _Pragma("unroll")                                                      \
        for (int rr_ = 0; rr_ < 8; rr_++) {                                    \
            int row_ = m0 + wm0 + (rr_ >> 1) * 16 + ((rr_ & 1) << 3) + g;      \
            const float* zr_ = g_z + (size_t)row_ * 448 + (W) * 32 + 2 * c;    \
            _Pragma("unroll")                                                  \
            for (int j_ = 0; j_ < 4; j_++) {                                   \
                float2 v_ = *(const float2*)(zr_ + 8 * j_);                    \
                zq_c[rr_][j_] = pack_bf16(v_.x, v_.y);                         \
            }                                                                  \
        }                                                                      \
    } while (0)

    LOAD_ZQ(0);

    float acc[4][4][4];
    #pragma unroll
    for (int mi = 0; mi < 4; mi++)
        #pragma unroll
        for (int nj = 0; nj < 4; nj++)
            #pragma unroll
            for (int k = 0; k < 4; k++) acc[mi][nj][k] = 0.f;

    // ldmatrix.trans lane offset: lanes 0-15 -> k rows 0..15 (n-lo), lanes 16-31 same rows (n+8)
    const uint32_t b_lrow = (uint32_t)((lane & 15) * BPITCH + ((lane >> 4) & 1) * 16);

    for (int s = 0; s < 336; s++) {
        CP_WAIT2();
        __syncthreads();                       // B[s] visible; buffer (s+3)&3 free
        if (s + 3 < 336) ISSUE_B(s + 3);
        CP_COMMIT();

        const int p = s % 24;
        // zp for this stage's 8 rows (broadcast LDS within each quad)
        uint32_t zp2[8];
        #pragma unroll
        for (int rr = 0; rr < 8; rr++) {
            int row = wm0 + (rr >> 1) * 16 + ((rr & 1) << 3) + g;
            float v = zp_s[row * 25 + p];
            zp2[rr] = pack_bf16(v, v);
        }

        const uint32_t B_base = sb + GOFF_B + (uint32_t)((s & 3) * BSTAGE);

        #pragma unroll
        for (int ks = 0; ks < 2; ks++) {
            // B fragments via ldmatrix.trans: matrices (k-lo,n-lo),(k-hi,n-lo),(k-lo,n-hi),(k-hi,n-hi)
            uint32_t bfr[2][4];
            #pragma unroll
            for (int njp = 0; njp < 2; njp++)
                LDSM4T(bfr[njp][0], bfr[njp][1], bfr[njp][2], bfr[njp][3],
                       B_base + (uint32_t)(ks * 16 * BPITCH + (wn0 + njp * 16) * 2) + b_lrow);

            #pragma unroll
            for (int mi = 0; mi < 4; mi++) {
                uint32_t a0 = hmul2(zp2[2 * mi],     zq_c[2 * mi][ks * 2]);
                uint32_t a1 = hmul2(zp2[2 * mi + 1], zq_c[2 * mi + 1][ks * 2]);
                uint32_t a2 = hmul2(zp2[2 * mi],     zq_c[2 * mi][ks * 2 + 1]);
                uint32_t a3 = hmul2(zp2[2 * mi + 1], zq_c[2 * mi + 1][ks * 2 + 1]);
                #pragma unroll
                for (int nj = 0; nj < 4; nj++) {
                    uint32_t b0 = bfr[nj >> 1][(nj & 1) * 2];
                    uint32_t b1 = bfr[nj >> 1][(nj & 1) * 2 + 1];
                    asm volatile(
                        "mma.sync.aligned.m16n8k16.row.col.f32.bf16.bf16.f32 "
                        "{%0,%1,%2,%3},{%4,%5,%6,%7},{%8,%9},{%0,%1,%2,%3};"
                        : "+f"(acc[mi][nj][0]), "+f"(acc[mi][nj][1]),
                          "+f"(acc[mi][nj][2]), "+f"(acc[mi][nj][3])
                        : "r"(a0), "r"(a1), "r"(a2), "r"(a3),
                          "r"(b0), "r"(b1));
                }
            }
        }

        // reload zq register cache at window boundary
        if (p == 23 && s + 1 < 336) LOAD_ZQ((s + 1) / 24);
    }

    // epilogue: write split partials
    #pragma unroll
    for (int mi = 0; mi < 4; mi++)
        #pragma unroll
        for (int nj = 0; nj < 4; nj++) {
            int row = m0 + wm0 + 16 * mi + g;
            int col = n0 + wn0 + 8 * nj + 2 * c;
            float* d0 = g_part + ((size_t)blockIdx.z * 512 + row) * 512 + col;
            float* d1 = g_part + ((size_t)blockIdx.z * 512 + row + 8) * 512 + col;
            *(float2*)d0 = make_float2(acc[mi][nj][0], acc[mi][nj][1]);
            *(float2*)d1 = make_float2(acc[mi][nj][2], acc[mi][nj][3]);
        }
}
#undef ISSUE_B
#undef LOAD_ZQ

// ---------------- kernel 4: reduce split-K partials + bias + relu ----------
__global__ void reduce_relu_kernel(const float* __restrict__ pb0) {
    int b = blockIdx.x;
    for (int j = threadIdx.x; j < 512; j += 256) {
        float s = pb0[j];
        #pragma unroll
        for (int sp = 0; sp < 18; sp++)
            s += g_part[((size_t)sp * 512 + b) * 512 + j];
        g_h1[(size_t)b * 512 + j] = fmaxf(s, 0.f);
    }
}

// ---------------- kernel 5: prediction MLP + sigmoid -----------------------
__global__ void pred_kernel(const float* __restrict__ pw1, const float* __restrict__ pb1,
                            const float* __restrict__ pw2, const float* __restrict__ pb2,
                            float* __restrict__ out) {
    __shared__ float h1s[4][512];
    __shared__ float h2s[4][256];
    __shared__ float red[4][8];
    const int r0 = blockIdx.x * 4;
    const int tid = threadIdx.x;

    for (int i = tid; i < 2048; i += 256)
        h1s[i >> 9][i & 511] = g_h1[(size_t)(r0 + (i >> 9)) * 512 + (i & 511)];
    __syncthreads();

    {
        float a[4];
        float b = pb1[tid];
        #pragma unroll
        for (int r = 0; r < 4; r++) a[r] = b;
        #pragma unroll 8
        for (int i = 0; i < 512; i++) {
            float w = pw1[i * 256 + tid];
            #pragma unroll
            for (int r = 0; r < 4; r++) a[r] += h1s[r][i] * w;
        }
        #pragma unroll
        for (int r = 0; r < 4; r++) h2s[r][tid] = fmaxf(a[r], 0.f);
    }
    __syncthreads();

    float w2 = pw2[tid];
    int lane = tid & 31, wp = tid >> 5;
    #pragma unroll
    for (int r = 0; r < 4; r++) {
        float v = h2s[r][tid] * w2;
        #pragma unroll
        for (int o = 16; o; o >>= 1) v += __shfl_xor_sync(0xffffffffu, v, o);
        if (lane == 0) red[r][wp] = v;
    }
    __syncthreads();
    if (tid < 4) {
        float s = pb2[0];
        #pragma unroll
        for (int w = 0; w < 8; w++) s += red[tid][w];
        out[r0 + tid] = 1.f / (1.f + expf(-s));
    }
}

// ---------------- launch ----------------------------------------------------
extern "C" void kernel_launch(void* const* d_in, const int* in_sizes, int n_in,
                              void* d_out, int out_size) {
    const float* x   = (const float*)d_in[0];
    const void*  sp  = d_in[1];
    const float* emb = (const float*)d_in[2];
    const float* dw0 = (const float*)d_in[3];
    const float* db0 = (const float*)d_in[4];
    const float* dw1 = (const float*)d_in[5];
    const float* db1 = (const float*)d_in[6];
    const float* dw2 = (const float*)d_in[7];
    const float* db2 = (const float*)d_in[8];
    const float* dw3 = (const float*)d_in[9];
    const float* db3 = (const float*)d_in[10];
    const float* pw0 = (const float*)d_in[11];
    const float* pb0 = (const float*)d_in[12];
    const float* pw1 = (const float*)d_in[13];
    const float* pb1 = (const float*)d_in[14];
    const float* pw2 = (const float*)d_in[15];
    const float* pb2 = (const float*)d_in[16];
    float* out = (float*)d_out;

    cudaFuncSetAttribute(inter_gemm_kernel,
                         cudaFuncAttributeMaxDynamicSharedMemorySize, (int)GSMEM);

    convert_w0_kernel<<<46656, 256>>>(pw0);   // 186624*512 / 8 / 256
    dense_mlp_kernel<<<128, 256>>>(x, dw0, db0, dw1, db1, dw2, db2, dw3, db3);
    embed_kernel<<<52, 256>>>(sp, emb);
    inter_gemm_kernel<<<dim3(4, 4, 18), 256, GSMEM>>>();
    reduce_relu_kernel<<<512, 256>>>(pb0);
    pred_kernel<<<128, 256>>>(pw1, pb1, pw2, pb2, out);
}

// round 11
// speedup vs baseline: 1.2887x; 1.0302x over previous
#include <cuda_runtime.h>
#include <cuda_bf16.h>
#include <math.h>
#include <stdint.h>

// ---------------- scratch (device globals; no allocs allowed) ----------------
__device__ float g_z[512 * 448];            // z padded to 448 cols (cols 432..447 = 0)
__device__ float g_part[18 * 512 * 512];    // split-K partials
__device__ float g_h1[512 * 512];           // relu(inter@pw0+pb0)
// W0 converted to bf16, SAME [k][n] layout (no transpose)
__device__ __nv_bfloat16 g_w0c[(size_t)186624 * 512];

// pack two fp32 -> bf16x2 (lo -> low half)
__device__ __forceinline__ uint32_t pack_bf16(float lo, float hi) {
    uint32_t r;
    asm("cvt.rn.bf16x2.f32 %0, %1, %2;" : "=r"(r) : "f"(hi), "f"(lo));
    return r;
}
__device__ __forceinline__ uint32_t hmul2(uint32_t a, uint32_t b) {
    uint32_t r;
    asm("mul.rn.bf16x2 %0, %1, %2;" : "=r"(r) : "r"(a), "r"(b));
    return r;
}
__device__ __forceinline__ uint32_t smem_u32(const void* p) {
    uint32_t a;
    asm("{ .reg .u64 t; cvta.to.shared.u64 t, %1; cvt.u32.u64 %0, t; }" : "=r"(a) : "l"(p));
    return a;
}
#define LDSM4T(R0, R1, R2, R3, ADDR)                                           \
    asm volatile("ldmatrix.sync.aligned.m8n8.x4.trans.shared.b16 {%0,%1,%2,%3}, [%4];" \
                 : "=r"(R0), "=r"(R1), "=r"(R2), "=r"(R3) : "r"(ADDR))
__device__ __forceinline__ void cpasync32(uint32_t dst, const void* src) {
    asm volatile(
        "cp.async.cg.shared.global [%0], [%1], 16;\n\t"
        "cp.async.cg.shared.global [%2], [%3], 16;"
        :: "r"(dst), "l"(src), "r"(dst + 16), "l"((const char*)src + 16) : "memory");
}
#define CP_COMMIT() asm volatile("cp.async.commit_group;" ::: "memory")
#define CP_WAIT2()  asm volatile("cp.async.wait_group 2;" ::: "memory")

// ---------------- kernel 0: elementwise convert W0 -> bf16 (streaming) ------
__global__ void convert_w0_kernel(const float* __restrict__ W0) {
    size_t i = ((size_t)blockIdx.x * 256 + threadIdx.x) * 8;
    float4 a = __ldcs((const float4*)(W0 + i));
    float4 b = __ldcs((const float4*)(W0 + i + 4));
    uint4 o;
    o.x = pack_bf16(a.x, a.y); o.y = pack_bf16(a.z, a.w);
    o.z = pack_bf16(b.x, b.y); o.w = pack_bf16(b.z, b.w);
    __stcs((uint4*)(g_w0c + i), o);
}

// ---------------- kernel 1: dense MLP (4 batch rows / block) ----------------
__global__ void dense_mlp_kernel(const float* __restrict__ x,
                                 const float* __restrict__ dw0, const float* __restrict__ db0,
                                 const float* __restrict__ dw1, const float* __restrict__ db1,
                                 const float* __restrict__ dw2, const float* __restrict__ db2,
                                 const float* __restrict__ dw3, const float* __restrict__ db3) {
    __shared__ float xs[4][13];
    __shared__ float h0[4][512];
    __shared__ float h1[4][256];
    __shared__ float h2[4][64];
    const int r0 = blockIdx.x * 4;
    const int tid = threadIdx.x;

    if (tid < 52) xs[tid / 13][tid % 13] = x[(r0 + tid / 13) * 13 + tid % 13];
    __syncthreads();

    #pragma unroll
    for (int jj = 0; jj < 2; jj++) {
        int j = tid + jj * 256;
        float a[4];
        float b = db0[j];
        #pragma unroll
        for (int r = 0; r < 4; r++) a[r] = b;
        #pragma unroll
        for (int i = 0; i < 13; i++) {
            float w = dw0[i * 512 + j];
            #pragma unroll
            for (int r = 0; r < 4; r++) a[r] += xs[r][i] * w;
        }
        #pragma unroll
        for (int r = 0; r < 4; r++) h0[r][j] = fmaxf(a[r], 0.f);
    }
    __syncthreads();

    {
        float a[4];
        float b = db1[tid];
        #pragma unroll
        for (int r = 0; r < 4; r++) a[r] = b;
        #pragma unroll 8
        for (int i = 0; i < 512; i++) {
            float w = dw1[i * 256 + tid];
            #pragma unroll
            for (int r = 0; r < 4; r++) a[r] += h0[r][i] * w;
        }
        #pragma unroll
        for (int r = 0; r < 4; r++) h1[r][tid] = fmaxf(a[r], 0.f);
    }
    __syncthreads();

    if (tid < 64) {
        float a[4];
        float b = db2[tid];
        #pragma unroll
        for (int r = 0; r < 4; r++) a[r] = b;
        #pragma unroll 8
        for (int i = 0; i < 256; i++) {
            float w = dw2[i * 64 + tid];
            #pragma unroll
            for (int r = 0; r < 4; r++) a[r] += h1[r][i] * w;
        }
        #pragma unroll
        for (int r = 0; r < 4; r++) h2[r][tid] = fmaxf(a[r], 0.f);
    }
    __syncthreads();

    if (tid < 16) {
        float a[4];
        float b = db3[tid];
        #pragma unroll
        for (int r = 0; r < 4; r++) a[r] = b;
        #pragma unroll
        for (int i = 0; i < 64; i++) {
            float w = dw3[i * 16 + tid];
            #pragma unroll
            for (int r = 0; r < 4; r++) a[r] += h2[r][i] * w;
        }
        #pragma unroll
        for (int r = 0; r < 4; r++) g_z[(size_t)(r0 + r) * 448 + tid] = a[r];
    }
    if (tid >= 64 && tid < 128) {
        int u = tid - 64;
        g_z[(size_t)(r0 + u / 16) * 448 + 432 + (u % 16)] = 0.f;
    }
}

// ---------------- kernel 2: embedding gather -> z[:,16:432] ----------------
__global__ void embed_kernel(const void* __restrict__ sp, const float* __restrict__ emb) {
    int t = blockIdx.x * blockDim.x + threadIdx.x;
    if (t >= 512 * 26) return;
    const int* si = (const int*)sp;
    bool is64 = (si[1] == 0 && si[3] == 0 && si[5] == 0);
    long long v = is64 ? ((const long long*)sp)[t] : (long long)si[t];
    int id = (int)((v + 1) % 100000);
    int b = t / 26, f = t - b * 26;
    const float4* src = (const float4*)(emb + ((size_t)f * 100000 + id) * 16);
    float4* dst = (float4*)(g_z + (size_t)b * 448 + 16 + f * 16);
    dst[0] = src[0]; dst[1] = src[1]; dst[2] = src[2]; dst[3] = src[3];
}

// ---------------- kernel 3: interaction GEMM -------------------------------
// C[512,512] = A @ W0, A[b, p*432+q] = z[b,p]*z[b,q]
// CTA: 128m x 128n, 24 p per split (18 splits -> 288 CTAs = 2/SM).
// BK=64 stage: TWO consecutive p-values sharing one zq-window register cache.
// 12 p-pairs * 14 q-windows = 168 stages (half the syncs of R10).
// B: bf16 W0c [k][n] rows cp.async'd ([2][32k][128n], pitch 272B, 4-stage ring);
//    fragments via ldmatrix.x4.trans.
#define BPITCH  272u                        // bytes per k-row (128 bf16 + 16B pad)
#define BHALF   8704u                       // 32 * 272 (one p's k32 block)
#define BSTAGE  17408u                      // 2 halves
#define GOFF_ZP 0u                          // [128][25] f32 = 12800
#define GOFF_B  12800u                      // 4 x 17408
#define GSMEM   82432u

__global__ __launch_bounds__(256, 2) void inter_gemm_kernel() {
    extern __shared__ char smem[];
    const uint32_t sb = smem_u32(smem);
    float* zp_s = (float*)(smem + GOFF_ZP);   // row pitch 25 floats

    const int tid = threadIdx.x;
    const int warp = tid >> 5, lane = tid & 31;
    const int g = lane >> 2, c = lane & 3;
    const int m0 = blockIdx.x * 128;          // m fastest -> L2 dedupe of W0c stream
    const int n0 = blockIdx.y * 128;
    const int p0 = blockIdx.z * 24;
    const int wm0 = (warp >> 2) * 64, wn0 = (warp & 3) * 32;

    // ---- load zp [128][24] ----
    for (int i = tid; i < 128 * 24; i += 256) {
        int b = i / 24, j = i - b * 24;
        zp_s[b * 25 + j] = g_z[(size_t)(m0 + b) * 448 + p0 + j];
    }
    __syncthreads();

    // ---- B cp.async params: thread -> (k row, 32B n-chunk) ----
    const int brow = tid >> 3;                // k row 0..31
    const int bco = (tid & 7) * 16;           // bf16 element offset (16 elems = 32B)
    const uint32_t bdst = sb + GOFF_B + (uint32_t)(brow * BPITCH + bco * 2);

    // stage T covers p-pair (2*(T%12), +1) of window T/12; one commit per stage
#define ISSUE_B(T) do {                                                        \
        int w_ = (T) / 12, pp_ = 2 * ((T) % 12);                               \
        long long gk0_ = (long long)(p0 + pp_) * 432 + w_ * 32 + brow;         \
        long long gk1_ = gk0_ + 432;                                           \
        if (gk0_ > 186623LL) gk0_ = 186623LL;                                  \
        if (gk1_ > 186623LL) gk1_ = 186623LL;                                  \
        uint32_t d_ = bdst + ((T) & 3) * BSTAGE;                               \
        cpasync32(d_,         g_w0c + gk0_ * 512 + n0 + bco);                  \
        cpasync32(d_ + BHALF, g_w0c + gk1_ * 512 + n0 + bco);                  \
    } while (0)

    ISSUE_B(0); CP_COMMIT();
    ISSUE_B(1); CP_COMMIT();
    ISSUE_B(2); CP_COMMIT();

    // ---- zq register cache: 8 rows x 4 k-pair slots (k = 2c + 8j) ----
    uint32_t zq_c[8][4];
#define LOAD_ZQ(W) do {                                                        \
        _Pragma("unroll")                                                      \
        for (int rr_ = 0; rr_ < 8; rr_++) {                                    \
            int row_ = m0 + wm0 + (rr_ >> 1) * 16 + ((rr_ & 1) << 3) + g;      \
            const float* zr_ = g_z + (size_t)row_ * 448 + (W) * 32 + 2 * c;    \
            _Pragma("unroll")                                                  \
            for (int j_ = 0; j_ < 4; j_++) {                                   \
                float2 v_ = *(const float2*)(zr_ + 8 * j_);                    \
                zq_c[rr_][j_] = pack_bf16(v_.x, v_.y);                         \
            }                                                                  \
        }                                                                      \
    } while (0)

    LOAD_ZQ(0);

    float acc[4][4][4];
    #pragma unroll
    for (int mi = 0; mi < 4; mi++)
        #pragma unroll
        for (int nj = 0; nj < 4; nj++)
            #pragma unroll
            for (int k = 0; k < 4; k++) acc[mi][nj][k] = 0.f;

    // ldmatrix.trans lane offset: lanes 0-15 -> k rows 0..15, lanes 16-31 -> n+8 halves
    const uint32_t b_lrow = (uint32_t)((lane & 15) * BPITCH + ((lane >> 4) & 1) * 16);

    for (int t = 0; t < 168; t++) {
        CP_WAIT2();
        __syncthreads();                       // B[t] visible; buffer (t+3)&3 free
        if (t + 3 < 168) ISSUE_B(t + 3);
        CP_COMMIT();

        const int pbase = 2 * (t % 12);
        const uint32_t S_base = sb + GOFF_B + (uint32_t)((t & 3) * BSTAGE);

        #pragma unroll
        for (int half = 0; half < 2; half++) {
            const int p = pbase + half;
            uint32_t zp2[8];
            #pragma unroll
            for (int rr = 0; rr < 8; rr++) {
                int row = wm0 + (rr >> 1) * 16 + ((rr & 1) << 3) + g;
                float v = zp_s[row * 25 + p];
                zp2[rr] = pack_bf16(v, v);
            }
            const uint32_t B_base = S_base + half * BHALF;

            #pragma unroll
            for (int ks = 0; ks < 2; ks++) {
                uint32_t bfr[2][4];
                #pragma unroll
                for (int njp = 0; njp < 2; njp++)
                    LDSM4T(bfr[njp][0], bfr[njp][1], bfr[njp][2], bfr[njp][3],
                           B_base + (uint32_t)(ks * 16 * BPITCH + (wn0 + njp * 16) * 2) + b_lrow);

                #pragma unroll
                for (int mi = 0; mi < 4; mi++) {
                    uint32_t a0 = hmul2(zp2[2 * mi],     zq_c[2 * mi][ks * 2]);
                    uint32_t a1 = hmul2(zp2[2 * mi + 1], zq_c[2 * mi + 1][ks * 2]);
                    uint32_t a2 = hmul2(zp2[2 * mi],     zq_c[2 * mi][ks * 2 + 1]);
                    uint32_t a3 = hmul2(zp2[2 * mi + 1], zq_c[2 * mi + 1][ks * 2 + 1]);
                    #pragma unroll
                    for (int nj = 0; nj < 4; nj++) {
                        uint32_t b0 = bfr[nj >> 1][(nj & 1) * 2];
                        uint32_t b1 = bfr[nj >> 1][(nj & 1) * 2 + 1];
                        asm volatile(
                            "mma.sync.aligned.m16n8k16.row.col.f32.bf16.bf16.f32 "
                            "{%0,%1,%2,%3},{%4,%5,%6,%7},{%8,%9},{%0,%1,%2,%3};"
                            : "+f"(acc[mi][nj][0]), "+f"(acc[mi][nj][1]),
                              "+f"(acc[mi][nj][2]), "+f"(acc[mi][nj][3])
                            : "r"(a0), "r"(a1), "r"(a2), "r"(a3),
                              "r"(b0), "r"(b1));
                    }
                }
            }
        }

        // reload zq register cache at window boundary
        if ((t % 12) == 11 && t + 1 < 168) LOAD_ZQ((t + 1) / 12);
    }

    // epilogue: write split partials
    #pragma unroll
    for (int mi = 0; mi < 4; mi++)
        #pragma unroll
        for (int nj = 0; nj < 4; nj++) {
            int row = m0 + wm0 + 16 * mi + g;
            int col = n0 + wn0 + 8 * nj + 2 * c;
            float* d0 = g_part + ((size_t)blockIdx.z * 512 + row) * 512 + col;
            float* d1 = g_part + ((size_t)blockIdx.z * 512 + row + 8) * 512 + col;
            *(float2*)d0 = make_float2(acc[mi][nj][0], acc[mi][nj][1]);
            *(float2*)d1 = make_float2(acc[mi][nj][2], acc[mi][nj][3]);
        }
}
#undef ISSUE_B
#undef LOAD_ZQ

// ---------------- kernel 4: reduce split-K partials + bias + relu ----------
__global__ void reduce_relu_kernel(const float* __restrict__ pb0) {
    int b = blockIdx.x;
    for (int j = threadIdx.x; j < 512; j += 256) {
        float s = pb0[j];
        #pragma unroll
        for (int sp = 0; sp < 18; sp++)
            s += g_part[((size_t)sp * 512 + b) * 512 + j];
        g_h1[(size_t)b * 512 + j] = fmaxf(s, 0.f);
    }
}

// ---------------- kernel 5: prediction MLP + sigmoid -----------------------
__global__ void pred_kernel(const float* __restrict__ pw1, const float* __restrict__ pb1,
                            const float* __restrict__ pw2, const float* __restrict__ pb2,
                            float* __restrict__ out) {
    __shared__ float h1s[4][512];
    __shared__ float h2s[4][256];
    __shared__ float red[4][8];
    const int r0 = blockIdx.x * 4;
    const int tid = threadIdx.x;

    for (int i = tid; i < 2048; i += 256)
        h1s[i >> 9][i & 511] = g_h1[(size_t)(r0 + (i >> 9)) * 512 + (i & 511)];
    __syncthreads();

    {
        float a[4];
        float b = pb1[tid];
        #pragma unroll
        for (int r = 0; r < 4; r++) a[r] = b;
        #pragma unroll 8
        for (int i = 0; i < 512; i++) {
            float w = pw1[i * 256 + tid];
            #pragma unroll
            for (int r = 0; r < 4; r++) a[r] += h1s[r][i] * w;
        }
        #pragma unroll
        for (int r = 0; r < 4; r++) h2s[r][tid] = fmaxf(a[r], 0.f);
    }
    __syncthreads();

    float w2 = pw2[tid];
    int lane = tid & 31, wp = tid >> 5;
    #pragma unroll
    for (int r = 0; r < 4; r++) {
        float v = h2s[r][tid] * w2;
        #pragma unroll
        for (int o = 16; o; o >>= 1) v += __shfl_xor_sync(0xffffffffu, v, o);
        if (lane == 0) red[r][wp] = v;
    }
    __syncthreads();
    if (tid < 4) {
        float s = pb2[0];
        #pragma unroll
        for (int w = 0; w < 8; w++) s += red[tid][w];
        out[r0 + tid] = 1.f / (1.f + expf(-s));
    }
}

// ---------------- launch ----------------------------------------------------
extern "C" void kernel_launch(void* const* d_in, const int* in_sizes, int n_in,
                              void* d_out, int out_size) {
    const float* x   = (const float*)d_in[0];
    const void*  sp  = d_in[1];
    const float* emb = (const float*)d_in[2];
    const float* dw0 = (const float*)d_in[3];
    const float* db0 = (const float*)d_in[4];
    const float* dw1 = (const float*)d_in[5];
    const float* db1 = (const float*)d_in[6];
    const float* dw2 = (const float*)d_in[7];
    const float* db2 = (const float*)d_in[8];
    const float* dw3 = (const float*)d_in[9];
    const float* db3 = (const float*)d_in[10];
    const float* pw0 = (const float*)d_in[11];
    const float* pb0 = (const float*)d_in[12];
    const float* pw1 = (const float*)d_in[13];
    const float* pb1 = (const float*)d_in[14];
    const float* pw2 = (const float*)d_in[15];
    const float* pb2 = (const float*)d_in[16];
    float* out = (float*)d_out;

    cudaFuncSetAttribute(inter_gemm_kernel,
                         cudaFuncAttributeMaxDynamicSharedMemorySize, (int)GSMEM);

    convert_w0_kernel<<<46656, 256>>>(pw0);   // 186624*512 / 8 / 256
    dense_mlp_kernel<<<128, 256>>>(x, dw0, db0, dw1, db1, dw2, db2, dw3, db3);
    embed_kernel<<<52, 256>>>(sp, emb);
    inter_gemm_kernel<<<dim3(4, 4, 18), 256, GSMEM>>>();
    reduce_relu_kernel<<<512, 256>>>(pb0);
    pred_kernel<<<128, 256>>>(pw1, pb1, pw2, pb2, out);
}